// round 6
// baseline (speedup 1.0000x reference)
#include <cuda_runtime.h>
#include <cuda_bf16.h>

// BioTripletLoss: B=16384 rows, D=1024 fp32.
// pos = ||h+r-t||, neg = ||h+r-t[neg_idx]||
// dissim (rel==1): relu(0.6 - pos) + 0.5*exp(-pos)
// sim:             relu(pos - neg + 0.3) + 0.3*relu(0.1 - pos)
// out = mean over B.
//
// R6: persistent single-wave grid (608 CTAs = 4/SM x 152 SMs on GB300),
// grid-stride over rows with 1-deep software prefetch, and ZERO per-row
// barriers (per-row partial sums accumulated via smem atomicAdd; one
// __syncthreads at CTA end). L2 policy hints kept from R4:
//   h, r  -> evict_first (single-use streams)
//   t     -> evict_last  (reused by the gather; fits in L2)

#define DDIM 1024
#define NTHREADS 256
#define GRID 608
#define MAX_ROWS_PER_CTA 32   // ceil(16384/608)=27, padded

static constexpr float MARGIN = 0.3f;
static constexpr float MIN_POS_DIST = 0.1f;
static constexpr float PUSH_SCALE = 2.0f;

__global__ void zero_out_kernel(float* out) {
    out[0] = 0.0f;
}

__device__ __forceinline__ float4 ld_hint4(const float4* p, unsigned long long pol) {
    float4 v;
    asm("ld.global.nc.L2::cache_hint.v4.f32 {%0,%1,%2,%3}, [%4], %5;"
        : "=f"(v.x), "=f"(v.y), "=f"(v.z), "=f"(v.w)
        : "l"(p), "l"(pol));
    return v;
}

__global__ __launch_bounds__(NTHREADS, 4)
void triplet_loss_kernel(const float* __restrict__ h,
                         const float* __restrict__ t,
                         const float* __restrict__ r,
                         const int* __restrict__ relation_ids,
                         const int* __restrict__ neg_idx,
                         float* __restrict__ out,
                         int B) {
    __shared__ float s_pos[MAX_ROWS_PER_CTA];
    __shared__ float s_neg[MAX_ROWS_PER_CTA];

    const int tid = threadIdx.x;
    const int lane = tid & 31;

    if (tid < MAX_ROWS_PER_CTA) { s_pos[tid] = 0.0f; s_neg[tid] = 0.0f; }
    __syncthreads();

    unsigned long long pol_first, pol_last;
    asm("createpolicy.fractional.L2::evict_first.b64 %0, 1.0;" : "=l"(pol_first));
    asm("createpolicy.fractional.L2::evict_last.b64 %0, 1.0;"  : "=l"(pol_last));

    const float4* __restrict__ h4 = reinterpret_cast<const float4*>(h);
    const float4* __restrict__ r4 = reinterpret_cast<const float4*>(r);
    const float4* __restrict__ t4 = reinterpret_cast<const float4*>(t);
    const int V = DDIM / 4;  // 256 float4 per row == one per thread

    int row = blockIdx.x;

    // Prologue: load row 0's data
    int j = __ldg(&neg_idx[row]);
    float4 hv = ld_hint4(h4 + (size_t)row * V + tid, pol_first);
    float4 rv = ld_hint4(r4 + (size_t)row * V + tid, pol_first);
    float4 tv = ld_hint4(t4 + (size_t)row * V + tid, pol_last);
    float4 nv = ld_hint4(t4 + (size_t)j   * V + tid, pol_last);

    int k = 0;
    while (true) {
        const int nrow_raw = row + GRID;
        const bool more = nrow_raw < B;
        // Clamp so prefetch loads are always in-bounds (results discarded on
        // the last iteration) — keeps loads unconditional and front-batched.
        const int nrow = more ? nrow_raw : row;

        const int jn = __ldg(&neg_idx[nrow]);
        float4 hn = ld_hint4(h4 + (size_t)nrow * V + tid, pol_first);
        float4 rn = ld_hint4(r4 + (size_t)nrow * V + tid, pol_first);
        float4 tn = ld_hint4(t4 + (size_t)nrow * V + tid, pol_last);
        float4 nn = ld_hint4(t4 + (size_t)jn   * V + tid, pol_last);

        // Compute current row while next row's loads are in flight
        float hx = hv.x + rv.x, hy = hv.y + rv.y;
        float hz = hv.z + rv.z, hw = hv.w + rv.w;
        float d, ps = 0.0f, ns = 0.0f;
        d = hx - tv.x; ps += d*d;  d = hy - tv.y; ps += d*d;
        d = hz - tv.z; ps += d*d;  d = hw - tv.w; ps += d*d;
        d = hx - nv.x; ns += d*d;  d = hy - nv.y; ns += d*d;
        d = hz - nv.z; ns += d*d;  d = hw - nv.w; ns += d*d;

        #pragma unroll
        for (int off = 16; off > 0; off >>= 1) {
            ps += __shfl_xor_sync(0xFFFFFFFFu, ps, off);
            ns += __shfl_xor_sync(0xFFFFFFFFu, ns, off);
        }
        if (lane == 0) {
            atomicAdd(&s_pos[k], ps);
            atomicAdd(&s_neg[k], ns);
        }

        if (!more) break;
        hv = hn; rv = rn; tv = tn; nv = nn;
        row = nrow_raw;
        k++;
    }

    __syncthreads();

    const int nrows = k + 1;  // identical across the CTA
    if (tid < nrows) {
        const int rr = blockIdx.x + tid * GRID;
        float pos_dist = sqrtf(s_pos[tid]);
        float neg_dist = sqrtf(s_neg[tid]);
        float loss;
        if (__ldg(&relation_ids[rr]) == 1) {
            loss = fmaxf(MARGIN * PUSH_SCALE - pos_dist, 0.0f) + 0.5f * expf(-pos_dist);
        } else {
            loss = fmaxf(pos_dist - neg_dist + MARGIN, 0.0f)
                 + 0.3f * fmaxf(MIN_POS_DIST - pos_dist, 0.0f);
        }
        atomicAdd(out, loss * (1.0f / (float)B));
    }
}

extern "C" void kernel_launch(void* const* d_in, const int* in_sizes, int n_in,
                              void* d_out, int out_size) {
    const float* h = (const float*)d_in[0];
    const float* t = (const float*)d_in[1];
    const float* r = (const float*)d_in[2];
    const int* relation_ids = (const int*)d_in[3];
    const int* neg_idx = (const int*)d_in[4];
    float* out = (float*)d_out;

    const int B = in_sizes[3];  // element count of relation_ids

    zero_out_kernel<<<1, 1>>>(out);
    triplet_loss_kernel<<<GRID, NTHREADS>>>(h, t, r, relation_ids, neg_idx, out, B);
}

// round 7
// speedup vs baseline: 1.5854x; 1.5854x over previous
#include <cuda_runtime.h>
#include <cuda_bf16.h>

// BioTripletLoss: B=16384 rows, D=1024 fp32.
// pos = ||h+r-t||, neg = ||h+r-t[neg_idx]||
// dissim (rel==1): relu(0.6 - pos) + 0.5*exp(-pos)
// sim:             relu(pos - neg + 0.3) + 0.3*relu(0.1 - pos)
// out = mean over B.
//
// R7 = R5 (best shape: 2 rows/CTA, front-batched loads, regs ~30, occ 86%)
//    + plain-global cache_hint loads (drop .nc texture path)
//    + ONE atomicAdd per CTA instead of two.
// L2 policy: h, r -> evict_first (single-use); t -> evict_last (gather reuse).

#define DDIM 1024
#define NTHREADS 256
#define ROWS_PER_CTA 2

static constexpr float MARGIN = 0.3f;
static constexpr float MIN_POS_DIST = 0.1f;
static constexpr float PUSH_SCALE = 2.0f;

__global__ void zero_out_kernel(float* out) {
    out[0] = 0.0f;
}

// Plain global-path 128-bit load with L2 eviction policy (no .nc).
__device__ __forceinline__ float4 ld_hint4(const float4* p, unsigned long long pol) {
    float4 v;
    asm("ld.global.L2::cache_hint.v4.f32 {%0,%1,%2,%3}, [%4], %5;"
        : "=f"(v.x), "=f"(v.y), "=f"(v.z), "=f"(v.w)
        : "l"(p), "l"(pol));
    return v;
}

__device__ __forceinline__ float per_sample_loss(float ps, float ns, int rel) {
    float pos_dist = sqrtf(ps);
    float neg_dist = sqrtf(ns);
    float loss;
    if (rel == 1) {
        loss = fmaxf(MARGIN * PUSH_SCALE - pos_dist, 0.0f) + 0.5f * expf(-pos_dist);
    } else {
        loss = fmaxf(pos_dist - neg_dist + MARGIN, 0.0f)
             + 0.3f * fmaxf(MIN_POS_DIST - pos_dist, 0.0f);
    }
    return loss;
}

__global__ __launch_bounds__(NTHREADS)
void triplet_loss_kernel(const float* __restrict__ h,
                         const float* __restrict__ t,
                         const float* __restrict__ r,
                         const int* __restrict__ relation_ids,
                         const int* __restrict__ neg_idx,
                         float* __restrict__ out,
                         int B) {
    const int row0 = blockIdx.x * ROWS_PER_CTA;
    const int row1 = row0 + 1;
    const int tid = threadIdx.x;

    unsigned long long pol_first, pol_last;
    asm("createpolicy.fractional.L2::evict_first.b64 %0, 1.0;" : "=l"(pol_first));
    asm("createpolicy.fractional.L2::evict_last.b64 %0, 1.0;"  : "=l"(pol_last));

    const int j0 = __ldg(&neg_idx[row0]);
    const int j1 = __ldg(&neg_idx[row1]);

    const float4* __restrict__ h4 = reinterpret_cast<const float4*>(h);
    const float4* __restrict__ r4 = reinterpret_cast<const float4*>(r);
    const float4* __restrict__ t4 = reinterpret_cast<const float4*>(t);
    const int V = DDIM / 4;  // 256 float4 per row == one per thread

    // Front-batch all 8 loads (MLP = 8).
    float4 hv0 = ld_hint4(h4 + (size_t)row0 * V + tid, pol_first);
    float4 rv0 = ld_hint4(r4 + (size_t)row0 * V + tid, pol_first);
    float4 tv0 = ld_hint4(t4 + (size_t)row0 * V + tid, pol_last);
    float4 nv0 = ld_hint4(t4 + (size_t)j0   * V + tid, pol_last);
    float4 hv1 = ld_hint4(h4 + (size_t)row1 * V + tid, pol_first);
    float4 rv1 = ld_hint4(r4 + (size_t)row1 * V + tid, pol_first);
    float4 tv1 = ld_hint4(t4 + (size_t)row1 * V + tid, pol_last);
    float4 nv1 = ld_hint4(t4 + (size_t)j1   * V + tid, pol_last);

    float hx, hy, hz, hw, d;

    // Row 0
    hx = hv0.x + rv0.x; hy = hv0.y + rv0.y; hz = hv0.z + rv0.z; hw = hv0.w + rv0.w;
    float ps0 = 0.0f, ns0 = 0.0f;
    d = hx - tv0.x; ps0 += d*d;  d = hy - tv0.y; ps0 += d*d;
    d = hz - tv0.z; ps0 += d*d;  d = hw - tv0.w; ps0 += d*d;
    d = hx - nv0.x; ns0 += d*d;  d = hy - nv0.y; ns0 += d*d;
    d = hz - nv0.z; ns0 += d*d;  d = hw - nv0.w; ns0 += d*d;

    // Row 1
    hx = hv1.x + rv1.x; hy = hv1.y + rv1.y; hz = hv1.z + rv1.z; hw = hv1.w + rv1.w;
    float ps1 = 0.0f, ns1 = 0.0f;
    d = hx - tv1.x; ps1 += d*d;  d = hy - tv1.y; ps1 += d*d;
    d = hz - tv1.z; ps1 += d*d;  d = hw - tv1.w; ps1 += d*d;
    d = hx - nv1.x; ns1 += d*d;  d = hy - nv1.y; ns1 += d*d;
    d = hz - nv1.z; ns1 += d*d;  d = hw - nv1.w; ns1 += d*d;

    // Warp reduce all four accumulators
    #pragma unroll
    for (int off = 16; off > 0; off >>= 1) {
        ps0 += __shfl_xor_sync(0xFFFFFFFFu, ps0, off);
        ns0 += __shfl_xor_sync(0xFFFFFFFFu, ns0, off);
        ps1 += __shfl_xor_sync(0xFFFFFFFFu, ps1, off);
        ns1 += __shfl_xor_sync(0xFFFFFFFFu, ns1, off);
    }

    // Block reduce across 8 warps, one barrier
    __shared__ float s_ps0[NTHREADS / 32], s_ns0[NTHREADS / 32];
    __shared__ float s_ps1[NTHREADS / 32], s_ns1[NTHREADS / 32];
    __shared__ float s_loss1;
    const int lane = tid & 31;
    const int wid = tid >> 5;
    if (lane == 0) {
        s_ps0[wid] = ps0; s_ns0[wid] = ns0;
        s_ps1[wid] = ps1; s_ns1[wid] = ns1;
    }
    __syncthreads();

    // Warp 1 finalizes row 1 into smem; warp 0 finalizes row 0 and issues the
    // CTA's single atomic after a second barrier.
    if (tid == 32) {
        float ps = 0.0f, ns = 0.0f;
        #pragma unroll
        for (int w = 0; w < NTHREADS / 32; w++) { ps += s_ps1[w]; ns += s_ns1[w]; }
        s_loss1 = per_sample_loss(ps, ns, __ldg(&relation_ids[row1]));
    }
    __syncthreads();
    if (tid == 0) {
        float ps = 0.0f, ns = 0.0f;
        #pragma unroll
        for (int w = 0; w < NTHREADS / 32; w++) { ps += s_ps0[w]; ns += s_ns0[w]; }
        float loss = per_sample_loss(ps, ns, __ldg(&relation_ids[row0])) + s_loss1;
        atomicAdd(out, loss * (1.0f / (float)B));
    }
}

extern "C" void kernel_launch(void* const* d_in, const int* in_sizes, int n_in,
                              void* d_out, int out_size) {
    const float* h = (const float*)d_in[0];
    const float* t = (const float*)d_in[1];
    const float* r = (const float*)d_in[2];
    const int* relation_ids = (const int*)d_in[3];
    const int* neg_idx = (const int*)d_in[4];
    float* out = (float*)d_out;

    const int B = in_sizes[3];  // element count of relation_ids

    zero_out_kernel<<<1, 1>>>(out);
    triplet_loss_kernel<<<B / ROWS_PER_CTA, NTHREADS>>>(h, t, r, relation_ids, neg_idx, out, B);
}